// round 8
// baseline (speedup 1.0000x reference)
#include <cuda_runtime.h>
#include <cuda_bf16.h>
#include <stdint.h>

// Problem constants (fixed by the dataset)
#define B_   8
#define M_   50000
#define D_   256
#define NH_  8
#define GH_  16
#define OUT_ 256
#define SEL_CAP 2048

#define TILE_ROWS 256
#define TILES_PER_B 196              // ceil(50000/256)

// ---------------- scratch (device globals; no allocations) ----------------
__device__ __align__(16) float g_S[B_ * M_];
__device__ __align__(16) float g_colsum[B_ * D_];
__device__ float g_kth[B_];
__device__ int   g_selCount[B_];
__device__ int   g_selIdx[B_ * SEL_CAP];
__device__ __align__(16) float g_num[B_ * OUT_];
__device__ float g_den[B_ * NH_];
__device__ __align__(16) float g_v[B_ * OUT_];

// ---------------- helpers ----------------
__device__ __forceinline__ unsigned keyOf(float x) {
    unsigned u = __float_as_uint(x);
    return (u & 0x80000000u) ? ~u : (u | 0x80000000u);
}
__device__ __forceinline__ float invKey(unsigned k) {
    unsigned u = (k & 0x80000000u) ? (k & 0x7FFFFFFFu) : ~k;
    return __uint_as_float(u);
}

// f32x2 packed FMA (Blackwell sm_103a)
#define FMA2(acc, a, b) asm("fma.rn.f32x2 %0, %1, %2, %0;" : "+l"(acc) : "l"(a), "l"(b))
__device__ __forceinline__ unsigned long long packdup(float x) {
    unsigned long long r;
    unsigned xu = __float_as_uint(x);
    asm("mov.b64 %0, {%1, %1};" : "=l"(r) : "r"(xu));
    return r;
}
__device__ __forceinline__ float f2lo(unsigned long long v) {
    return __uint_as_float((unsigned)(v & 0xFFFFFFFFu));
}
__device__ __forceinline__ float f2hi(unsigned long long v) {
    return __uint_as_float((unsigned)(v >> 32));
}

// cp.async wrappers
__device__ __forceinline__ void cpa16(uint32_t dst, const void* src, int srcsz) {
    asm volatile("cp.async.cg.shared.global [%0], [%1], 16, %2;"
                 :: "r"(dst), "l"(src), "r"(srcsz));
}
__device__ __forceinline__ void cpa8(uint32_t dst, const void* src) {
    asm volatile("cp.async.ca.shared.global [%0], [%1], 8;"
                 :: "r"(dst), "l"(src));
}
#define CP_COMMIT() asm volatile("cp.async.commit_group;" ::: "memory")
#define CP_WAIT1()  asm volatile("cp.async.wait_group 1;" ::: "memory")

// ---------------- Z: zero scratch (3 launches; k1 is launch #4) ------------
__global__ void z_colsum() {
    int i = blockIdx.x * 256 + threadIdx.x;
    if (i < B_ * D_) g_colsum[i] = 0.f;
}
__global__ void z_num() {
    int i = blockIdx.x * 256 + threadIdx.x;
    if (i < B_ * OUT_) g_num[i] = 0.f;
}
__global__ void z_misc() {
    int i = threadIdx.x;
    if (i < B_ * NH_) g_den[i] = 0.f;
    if (i < B_)       g_selCount[i] = 0;
}

// ---------------- K1: gate scores S + column sums (cp.async pipeline) ------
// Tile = 256 rows. 8 chunks of 32 cols, DOUBLE-BUFFERED via cp.async:
// chunk N+2's loads are in flight while chunk N computes -> DRAM latency
// hidden by pipeline depth, no LDG->reg->STS round trip.
// Thread t: rows (t>>2)*4..+3, hidden units 4*(t&3)..+3 (2 f32x2 accs/row).
// Swizzle key (r>>2)&7: conflict-free STS(cp.async dst)/LDS for all phases.
// Smem: 2x32KB data + 2x2KB weights + 1KB csum = 69KB -> 3 blocks/SM.
__global__ __launch_bounds__(256, 3) void k1_gate(
    const float* __restrict__ h,
    const float* __restrict__ gsl1_w, const float* __restrict__ gsl1_b,
    const float* __restrict__ gsl2_w, const float* __restrict__ gsl2_b)
{
    extern __shared__ __align__(16) unsigned char smraw[];
    float4* stb = (float4*)smraw;                                    // [2][256*8] f4
    unsigned long long* wsb = (unsigned long long*)(smraw + 65536);  // [2][256] u64
    float* csum1 = (float*)(smraw + 65536 + 4096);                   // 256 f

    uint32_t sbase;
    asm("{.reg .u64 t; cvta.to.shared.u64 t, %1; cvt.u32.u64 %0, t;}"
        : "=r"(sbase) : "l"(smraw));

    const int tid  = threadIdx.x;
    const int b    = blockIdx.y;
    const int row0 = blockIdx.x * TILE_ROWS;
    const int hseg = tid & 3;            // hidden units 4*hseg..+3
    const int rg   = tid >> 2;           // rows rg*4..+3
    const int sw8  = tid & 7;
    const int q    = sw8 << 2;
    const int oct  = tid & 7, rseg = tid >> 3;  // colsum mapping

    csum1[tid] = 0.f;

    const float* hb = h + (size_t)b * M_ * D_;
    const unsigned long long* gw = (const unsigned long long*)gsl1_w; // [256][8]

    unsigned long long acc[4][2];
#pragma unroll
    for (int r = 0; r < 4; r++) { acc[r][0] = 0ULL; acc[r][1] = 0ULL; }

    // producer: issue chunk ch into buffer ch&1
    auto issue = [&](int ch) {
        const int buf = ch & 1;
        const int c0 = ch * 32;
        cpa8(sbase + 65536 + buf * 2048 + tid * 8, gw + c0 * 8 + tid);
        const uint32_t dbase = sbase + buf * 32768;
#pragma unroll
        for (int j = 0; j < 8; ++j) {
            int r = (tid + 256 * j) >> 3;          // octet fixed = sw8
            int gr = row0 + r;
            uint32_t dst = dbase + (uint32_t)(r * 8 + (sw8 ^ ((r >> 2) & 7))) * 16u;
            cpa16(dst, hb + (size_t)gr * D_ + c0 + q, (gr < M_) ? 16 : 0);
        }
        CP_COMMIT();
    };

    issue(0);
    issue(1);

    for (int ch = 0; ch < 8; ++ch) {
        const int buf = ch & 1;
        const int c0 = ch * 32;
        CP_WAIT1();
        __syncthreads();   // all threads' chunk-ch groups complete (+csum1 init)

        const float4* xb = stb + buf * 2048;
        const unsigned long long* wb = wsb + buf * 256;

        // compute: 8 col-groups of 4 cols
#pragma unroll
        for (int cg = 0; cg < 8; ++cg) {
            ulonglong2 w0 = *(const ulonglong2*)&wb[(cg * 4 + 0) * 8 + hseg * 2];
            ulonglong2 w1 = *(const ulonglong2*)&wb[(cg * 4 + 1) * 8 + hseg * 2];
            ulonglong2 w2 = *(const ulonglong2*)&wb[(cg * 4 + 2) * 8 + hseg * 2];
            ulonglong2 w3 = *(const ulonglong2*)&wb[(cg * 4 + 3) * 8 + hseg * 2];
            const int slot = cg ^ (rg & 7);
#pragma unroll
            for (int rr = 0; rr < 4; ++rr) {
                float4 x4 = xb[(rg * 4 + rr) * 8 + slot];
                unsigned long long xx;
                xx = packdup(x4.x); FMA2(acc[rr][0], xx, w0.x); FMA2(acc[rr][1], xx, w0.y);
                xx = packdup(x4.y); FMA2(acc[rr][0], xx, w1.x); FMA2(acc[rr][1], xx, w1.y);
                xx = packdup(x4.z); FMA2(acc[rr][0], xx, w2.x); FMA2(acc[rr][1], xx, w2.y);
                xx = packdup(x4.w); FMA2(acc[rr][0], xx, w3.x); FMA2(acc[rr][1], xx, w3.y);
            }
        }

        // colsum: thread sums octet `oct` over rows rseg*8..+7 (conflict-free)
        {
            float4 ca = make_float4(0.f, 0.f, 0.f, 0.f);
#pragma unroll
            for (int rr = 0; rr < 8; ++rr) {
                int r = rseg * 8 + rr;
                float4 v = xb[r * 8 + (oct ^ ((r >> 2) & 7))];
                ca.x += v.x; ca.y += v.y; ca.z += v.z; ca.w += v.w;
            }
            atomicAdd(&csum1[c0 + oct * 4 + 0], ca.x);
            atomicAdd(&csum1[c0 + oct * 4 + 1], ca.y);
            atomicAdd(&csum1[c0 + oct * 4 + 2], ca.z);
            atomicAdd(&csum1[c0 + oct * 4 + 3], ca.w);
        }
        __syncthreads();   // buffer free for reuse
        if (ch + 2 < 8) issue(ch + 2); else CP_COMMIT();  // keep group indices aligned
    }

    // epilogue: per-row z over this thread's 4 hidden units, reduce across
    // the 4 hseg lanes (bits 0-1), sigmoid, packed float4 store.
    {
        const int u0 = 4 * hseg;
        const float b1a = gsl1_b[u0 + 0], b1b = gsl1_b[u0 + 1];
        const float b1c = gsl1_b[u0 + 2], b1d = gsl1_b[u0 + 3];
        const float w2a = gsl2_w[u0 + 0], w2b = gsl2_w[u0 + 1];
        const float w2c = gsl2_w[u0 + 2], w2d = gsl2_w[u0 + 3];

        float zr[4];
#pragma unroll
        for (int rr = 0; rr < 4; ++rr) {
            float z = 0.f;
            z = fmaf(fmaxf(f2lo(acc[rr][0]) + b1a, 0.f), w2a, z);
            z = fmaf(fmaxf(f2hi(acc[rr][0]) + b1b, 0.f), w2b, z);
            z = fmaf(fmaxf(f2lo(acc[rr][1]) + b1c, 0.f), w2c, z);
            z = fmaf(fmaxf(f2hi(acc[rr][1]) + b1d, 0.f), w2d, z);
            z += __shfl_xor_sync(0xFFFFFFFFu, z, 1);
            z += __shfl_xor_sync(0xFFFFFFFFu, z, 2);
            zr[rr] = z;
        }
        if (hseg == 0) {
            const float b2 = gsl2_b[0];
            const int base = row0 + rg * 4;
            if (base + 4 <= M_) {
                float4 s;
                s.x = 1.0f / (1.0f + expf(-(zr[0] + b2)));
                s.y = 1.0f / (1.0f + expf(-(zr[1] + b2)));
                s.z = 1.0f / (1.0f + expf(-(zr[2] + b2)));
                s.w = 1.0f / (1.0f + expf(-(zr[3] + b2)));
                *(float4*)&g_S[(size_t)b * M_ + base] = s;
            }
        }
    }

    // flush column sums
    atomicAdd(&g_colsum[b * D_ + tid], csum1[tid]);
}

// ---------------- K2: exact k-th largest per batch + mask + gather --------
__global__ __launch_bounds__(1024) void k2_select(const int* __restrict__ kptr,
                                                  float* __restrict__ outmask)
{
    const int b = blockIdx.x;
    __shared__ unsigned hist[256];
    __shared__ unsigned sh_prefix;
    __shared__ int sh_kneed;

    int kk = kptr ? *kptr : 500;
    if (kk <= 0 || kk > M_) {
        float kf = __int_as_float(kk);
        if (kf >= 1.f && kf <= (float)M_) kk = (int)kf;
        else kk = kk < 1 ? 1 : M_;
    }
    if (kk > M_) kk = M_;

    if (threadIdx.x == 0) { sh_prefix = 0u; sh_kneed = kk; }
    __syncthreads();

    const float* Sb = &g_S[(size_t)b * M_];
    const int NT = 1024;
    const int ITERS = (M_ + NT - 1) / NT;

    for (int pass = 3; pass >= 0; --pass) {
        for (int i = threadIdx.x; i < 256; i += NT) hist[i] = 0u;
        __syncthreads();
        const unsigned pre = sh_prefix;
        const int shift = pass * 8;
        const unsigned himask = (pass == 3) ? 0u : (0xFFFFFFFFu << (shift + 8));

        for (int it = 0; it < ITERS; ++it) {
            const int i = it * NT + threadIdx.x;
            const bool inb = (i < M_);
            unsigned key = inb ? keyOf(Sb[i]) : 0u;
            bool part = inb && (((key ^ pre) & himask) == 0u);
            unsigned act = __ballot_sync(0xFFFFFFFFu, part);
            if (part) {
                int bin = (key >> shift) & 255;
                unsigned peers = __match_any_sync(act, bin);
                int leader = __ffs(peers) - 1;
                if ((int)(threadIdx.x & 31) == leader)
                    atomicAdd(&hist[bin], (unsigned)__popc(peers));
            }
        }
        __syncthreads();
        if (threadIdx.x == 0) {
            int need = sh_kneed;
            unsigned cum = 0; int bin = 0;
            for (int v = 255; v >= 0; --v) {
                if (cum + hist[v] >= (unsigned)need) { bin = v; break; }
                cum += hist[v];
            }
            sh_prefix = pre | ((unsigned)bin << shift);
            sh_kneed = need - (int)cum;
        }
        __syncthreads();
    }
    const float kth = invKey(sh_prefix);
    if (threadIdx.x == 0) g_kth[b] = kth;

    // fused mask + gather (ragged loop fine: no warp-sync ops)
    for (int i = threadIdx.x; i < M_; i += NT) {
        float s = Sb[i];
        bool sel = s >= kth;
        outmask[b * M_ + i] = sel ? 1.f : 0.f;
        if (sel) {
            int pos = atomicAdd(&g_selCount[b], 1);
            if (pos < SEL_CAP) g_selIdx[b * SEL_CAP + pos] = i;
        }
    }
}

// ---------------- K4: selected-row correction (num / den) -----------------
#define RS 16
__global__ __launch_bounds__(256) void k4_selected(
    const float* __restrict__ h,
    const float* __restrict__ att_w, const float* __restrict__ att_b,
    const float* __restrict__ w_w)
{
    __shared__ __align__(16) float hsh[RS][D_];
    __shared__ float efac[RS][NH_];
    __shared__ float aw[D_ * NH_];

    const int b = blockIdx.y;
    const int tid = threadIdx.x;
    for (int i = tid; i < D_ * NH_; i += 256) aw[i] = att_w[i];

    int cnt = g_selCount[b];
    if (cnt > SEL_CAP) cnt = SEL_CAP;
    const int ngroups = (cnt + RS - 1) / RS;
    const float* hb = h + (size_t)b * M_ * D_;

    for (int g = blockIdx.x; g < ngroups; g += gridDim.x) {
        __syncthreads();
        for (int i = tid; i < RS * (D_ / 4); i += 256) {
            int r = i >> 6, c4 = (i & 63) << 2;
            int si = g * RS + r;
            float4 v = make_float4(0.f, 0.f, 0.f, 0.f);
            if (si < cnt)
                v = *(const float4*)(hb + (size_t)g_selIdx[b * SEL_CAP + si] * D_ + c4);
            *(float4*)&hsh[r][c4] = v;
        }
        __syncthreads();
        if (tid < RS * NH_) {
            int r = tid >> 3, hd = tid & 7;
            float s = 0.f;
            for (int c = 0; c < D_; c++) s = fmaf(hsh[r][c], aw[c * NH_ + hd], s);
            float a = fmaxf(s + att_b[hd], 0.f);
            efac[r][hd] = (g * RS + r < cnt) ? (expf(a) - 1.f) : 0.f;
        }
        __syncthreads();

        const int e = tid;
        float acc[RS];
#pragma unroll
        for (int r = 0; r < RS; r++) acc[r] = 0.f;
        for (int c4 = 0; c4 < D_; c4 += 4) {
            float w0 = __ldg(&w_w[(c4 + 0) * OUT_ + e]);
            float w1 = __ldg(&w_w[(c4 + 1) * OUT_ + e]);
            float w2 = __ldg(&w_w[(c4 + 2) * OUT_ + e]);
            float w3 = __ldg(&w_w[(c4 + 3) * OUT_ + e]);
#pragma unroll
            for (int r = 0; r < RS; r++) {
                float4 hv = *(const float4*)&hsh[r][c4];
                float a = acc[r];
                a = fmaf(hv.x, w0, a);
                a = fmaf(hv.y, w1, a);
                a = fmaf(hv.z, w2, a);
                a = fmaf(hv.w, w3, a);
                acc[r] = a;
            }
        }
        const int hd = e >> 5;
        float s = 0.f;
#pragma unroll
        for (int r = 0; r < RS; r++) s = fmaf(efac[r][hd], acc[r], s);
        atomicAdd(&g_num[b * OUT_ + e], s);
        if (tid < NH_) {
            float d = 0.f;
#pragma unroll
            for (int r = 0; r < RS; r++) d += efac[r][tid];
            atomicAdd(&g_den[b * NH_ + tid], d);
        }
    }
}

// ---------------- K5a: base term + Q_res + combine (col-parallel) ---------
__global__ __launch_bounds__(256) void k5a(
    const float* __restrict__ w_w,
    const float* __restrict__ res_w, const float* __restrict__ res_b)
{
    const int b = blockIdx.y;
    const int e = blockIdx.x * 32 + (threadIdx.x >> 3);
    const int l8 = threadIdx.x & 7;
    __shared__ float cs[D_];
    cs[threadIdx.x] = g_colsum[b * D_ + threadIdx.x];
    __syncthreads();

    float base = 0.f, qr = 0.f;
#pragma unroll 8
    for (int i = 0; i < 32; i++) {
        int c = l8 + 8 * i;
        float x = cs[c];
        base = fmaf(x, __ldg(&w_w[c * OUT_ + e]), base);
        qr   = fmaf(x, __ldg(&res_w[c * OUT_ + e]), qr);
    }
#pragma unroll
    for (int m = 1; m < 8; m <<= 1) {
        base += __shfl_xor_sync(0xFFFFFFFFu, base, m);
        qr   += __shfl_xor_sync(0xFFFFFFFFu, qr, m);
    }
    if (l8 == 0) {
        float Qres = fmaxf(qr * (1.0f / (float)M_) + res_b[e], 0.f);
        float den = (float)M_ + g_den[b * NH_ + (e >> 5)];
        float ov = (base + g_num[b * OUT_ + e]) / den;
        g_v[b * OUT_ + e] = fmaxf(ov + Qres, 0.f);
    }
}

// ---------------- K5b: layernorm of the 256-vector ------------------------
__global__ __launch_bounds__(256) void k5b(float* __restrict__ out)
{
    const int b = blockIdx.x;
    const int e = threadIdx.x;
    __shared__ float red[256];

    float v = g_v[b * OUT_ + e];
    red[e] = v; __syncthreads();
    for (int s = 128; s > 0; s >>= 1) {
        if (e < s) red[e] += red[e + s];
        __syncthreads();
    }
    float mean = red[0] * (1.0f / 256.0f);
    __syncthreads();
    float dm = v - mean;
    red[e] = dm * dm; __syncthreads();
    for (int s = 128; s > 0; s >>= 1) {
        if (e < s) red[e] += red[e + s];
        __syncthreads();
    }
    float var = red[0] * (1.0f / 256.0f);
    out[b * OUT_ + e] = dm * rsqrtf(var + 1e-8f);
}

// ---------------- launch -----------------
#define K1_SMEM (65536 + 4096 + 1024)

extern "C" void kernel_launch(void* const* d_in, const int* in_sizes, int n_in,
                              void* d_out, int out_size)
{
    const float* h      = (const float*)d_in[0];
    const float* att_w  = (const float*)d_in[1];
    const float* att_b  = (const float*)d_in[2];
    const float* w_w    = (const float*)d_in[3];
    const float* res_w  = (const float*)d_in[4];
    const float* res_b  = (const float*)d_in[5];
    const float* gsl1_w = (const float*)d_in[6];
    const float* gsl1_b = (const float*)d_in[7];
    const float* gsl2_w = (const float*)d_in[8];
    const float* gsl2_b = (const float*)d_in[9];
    const int*   kptr   = (n_in > 10) ? (const int*)d_in[10] : nullptr;

    float* out  = (float*)d_out;              // [B, 1, OUT] -> 2048 floats
    float* mask = out + B_ * OUT_;            // [B, 1, M]   -> 400000 floats

    cudaFuncSetAttribute(k1_gate, cudaFuncAttributeMaxDynamicSharedMemorySize, K1_SMEM);

    // launches 1-3: zeroing (k1 is launch #4 for ncu)
    z_colsum<<<8, 256>>>();
    z_num<<<8, 256>>>();
    z_misc<<<1, 128>>>();

    {
        dim3 grid(TILES_PER_B, B_);   // 196 x 8 = 1568 blocks, 3/SM
        k1_gate<<<grid, 256, K1_SMEM>>>(h, gsl1_w, gsl1_b, gsl2_w, gsl2_b);
    }
    k2_select<<<B_, 1024>>>(kptr, mask);
    {
        dim3 grid(64, B_);
        k4_selected<<<grid, 256>>>(h, att_w, att_b, w_w);
    }
    {
        dim3 grid(8, B_);
        k5a<<<grid, 256>>>(w_w, res_w, res_b);
    }
    k5b<<<B_, 256>>>(out);
}